// round 15
// baseline (speedup 1.0000x reference)
#include <cuda_runtime.h>
#include <cuda_fp16.h>
#include <cstdint>
#include <math.h>

#define NTOK 8192
#define HDIM 1024
#define FDIM 4096
#define NEXP 8
#define NROWS (NTOK*2)
#define HALF_RT 68

// ---------------- device scratch (allocation-free) ----------------
__device__ int    g_cnt[NEXP];
__device__ int    g_fill[NEXP];
__device__ int    g_off[NEXP+1];
__device__ int    g_tp[NEXP+1];
__device__ int    g_done;
__device__ int    g_tok_e[NTOK*2];
__device__ float  g_tok_w[NTOK*2];
__device__ int    g_pos[NTOK*2];
__device__ int    g_row_token[NROWS];
__device__ __half g_hidden[(size_t)NROWS*FDIM];   // grouped hidden (fp16)
__device__ __half g_xh[(size_t)NTOK*HDIM];        // x fp16 (written by router)
__device__ __half g_w1h[(size_t)NEXP*HDIM*FDIM];  // w1 fp16 [e][H][F]
__device__ __half g_w2h[(size_t)NEXP*FDIM*HDIM];  // w2 fp16 [e][F][H]
__device__ __half g_eout[(size_t)NROWS*HDIM];     // per-row GEMM2 out fp16

// ---------------- helpers ----------------
__device__ __forceinline__ uint32_t smem_u32(const void* p) {
    uint32_t a;
    asm("{ .reg .u64 t; cvta.to.shared.u64 t, %1; cvt.u32.u64 %0, t; }" : "=r"(a) : "l"(p));
    return a;
}
#define CPA16(dst,src,sz) asm volatile("cp.async.cg.shared.global [%0],[%1],16,%2;" :: "r"(dst), "l"(src), "r"(sz))
#define CPA_COMMIT() asm volatile("cp.async.commit_group;" ::: "memory")
#define CPA_WAIT2()  asm volatile("cp.async.wait_group 2;" ::: "memory")

__device__ __forceinline__ void ldsm_x4(uint32_t& r0, uint32_t& r1, uint32_t& r2, uint32_t& r3, uint32_t a) {
    asm volatile("ldmatrix.sync.aligned.m8n8.x4.shared.b16 {%0,%1,%2,%3},[%4];"
                 : "=r"(r0), "=r"(r1), "=r"(r2), "=r"(r3) : "r"(a));
}
__device__ __forceinline__ void ldsm_x4t(uint32_t& r0, uint32_t& r1, uint32_t& r2, uint32_t& r3, uint32_t a) {
    asm volatile("ldmatrix.sync.aligned.m8n8.x4.trans.shared.b16 {%0,%1,%2,%3},[%4];"
                 : "=r"(r0), "=r"(r1), "=r"(r2), "=r"(r3) : "r"(a));
}
__device__ __forceinline__ void mma16816(float* c, const uint32_t* a, const uint32_t* b) {
    asm volatile("mma.sync.aligned.m16n8k16.row.col.f32.f16.f16.f32 "
                 "{%0,%1,%2,%3},{%4,%5,%6,%7},{%8,%9},{%0,%1,%2,%3};"
                 : "+f"(c[0]), "+f"(c[1]), "+f"(c[2]), "+f"(c[3])
                 : "r"(a[0]), "r"(a[1]), "r"(a[2]), "r"(a[3]), "r"(b[0]), "r"(b[1]));
}
__device__ __forceinline__ float gelu_exact(float v) {
    return 0.5f * v * (1.f + erff(v * 0.70710678118654752f));
}

// ---------------- small kernels ----------------
__global__ void k_init0() {
    int i = threadIdx.x;
    if (i < NEXP) { g_cnt[i] = 0; g_fill[i] = 0; }
    if (i == 0) g_done = 0;
}
__global__ void k_convert_w1(const float4* __restrict__ w1, uint2* __restrict__ w1h) {
    const int NW = NEXP*HDIM*FDIM/4;
    for (int i = blockIdx.x * blockDim.x + threadIdx.x; i < NW; i += gridDim.x * blockDim.x) {
        float4 v = w1[i];
        __half2 a = __floats2half2_rn(v.x, v.y);
        __half2 b = __floats2half2_rn(v.z, v.w);
        w1h[i] = make_uint2(*(uint32_t*)&a, *(uint32_t*)&b);
    }
}
__global__ void k_convert_w2(const float4* __restrict__ w2, uint2* __restrict__ w2h) {
    const int NW = NEXP*HDIM*FDIM/4;
    for (int i = blockIdx.x * blockDim.x + threadIdx.x; i < NW; i += gridDim.x * blockDim.x) {
        float4 v = w2[i];
        __half2 a = __floats2half2_rn(v.x, v.y);
        __half2 b = __floats2half2_rn(v.z, v.w);
        w2h[i] = make_uint2(*(uint32_t*)&a, *(uint32_t*)&b);
    }
}

// router: top-2 selection + fused x->fp16 conversion + fused offsets + fused scatter
__global__ void k_router(const float4* __restrict__ x4,
                         const float4* __restrict__ rw4,
                         const float* __restrict__ rb,
                         uint2* __restrict__ xh2) {
    int warp = (blockIdx.x * blockDim.x + threadIdx.x) >> 5;
    int lane = threadIdx.x & 31;
    if (warp < NTOK) {
        const int Q = HDIM / 4;          // 256 float4 per row
        float acc[NEXP];
#pragma unroll
        for (int e = 0; e < NEXP; e++) acc[e] = 0.f;
#pragma unroll
        for (int j = 0; j < Q / 32; j++) {
            int idx = j * 32 + lane;
            float4 v = __ldg(x4 + (size_t)warp * Q + idx);
#pragma unroll
            for (int e = 0; e < NEXP; e++) {
                float4 w = __ldg(rw4 + (size_t)e * Q + idx);
                acc[e] = fmaf(v.x, w.x, acc[e]);
                acc[e] = fmaf(v.y, w.y, acc[e]);
                acc[e] = fmaf(v.z, w.z, acc[e]);
                acc[e] = fmaf(v.w, w.w, acc[e]);
            }
            // fused x -> fp16 store
            __half2 a = __floats2half2_rn(v.x, v.y);
            __half2 b = __floats2half2_rn(v.z, v.w);
            xh2[(size_t)warp * Q + idx] = make_uint2(*(uint32_t*)&a, *(uint32_t*)&b);
        }
#pragma unroll
        for (int o = 16; o > 0; o >>= 1)
#pragma unroll
            for (int e = 0; e < NEXP; e++)
                acc[e] += __shfl_xor_sync(0xffffffffu, acc[e], o);
        if (lane == 0) {
            float l[NEXP];
#pragma unroll
            for (int e = 0; e < NEXP; e++) l[e] = acc[e] + rb[e];
            int i0 = 0; float b0 = l[0];
#pragma unroll
            for (int e = 1; e < NEXP; e++) if (l[e] > b0) { b0 = l[e]; i0 = e; }
            int i1 = (i0 == 0) ? 1 : 0; float b1 = -3.4e38f;
#pragma unroll
            for (int e = 0; e < NEXP; e++)
                if (e != i0 && l[e] > b1) { b1 = l[e]; i1 = e; }
            float w0 = 1.f / (1.f + expf(b1 - b0));
            g_tok_e[warp*2]   = i0;  g_tok_e[warp*2+1] = i1;
            g_tok_w[warp*2]   = w0;  g_tok_w[warp*2+1] = 1.f - w0;
            atomicAdd(&g_cnt[i0], 1);
            atomicAdd(&g_cnt[i1], 1);
        }
    }
    __syncthreads();
    // last block: compute prefix offsets, then perform the scatter inline
    __shared__ int s_last;
    if (threadIdx.x == 0) {
        __threadfence();
        int prev = atomicAdd(&g_done, 1);
        s_last = (prev == gridDim.x - 1) ? 1 : 0;
        if (s_last) {
            g_off[0] = 0; g_tp[0] = 0;
            for (int e = 0; e < NEXP; e++) {
                g_off[e+1] = g_off[e] + g_cnt[e];
                g_tp[e+1]  = g_tp[e]  + (g_cnt[e] + 127) / 128;
            }
        }
    }
    __syncthreads();
    if (s_last) {
        // all other blocks' g_tok_e/g_tok_w stores are visible (fence+atomic chain)
        for (int i = threadIdx.x; i < NTOK * 2; i += blockDim.x) {
            int e = g_tok_e[i];
            int r = g_off[e] + atomicAdd(&g_fill[e], 1);
            g_row_token[r] = i >> 1;
            g_pos[i] = r;
        }
        __threadfence();
    }
}
// combine: out[tok] = w0*eout[r0] + w1*eout[r1], 8 elems per thread
__global__ void k_combine(float* __restrict__ out) {
    int idx = blockIdx.x * blockDim.x + threadIdx.x;
    if (idx >= NTOK * HDIM / 8) return;
    int tok = idx / (HDIM / 8);
    int c8  = (idx % (HDIM / 8)) * 8;
    float w0 = g_tok_w[tok*2], w1 = g_tok_w[tok*2+1];
    int   r0 = g_pos[tok*2],  r1 = g_pos[tok*2+1];
    uint4 pa = *(const uint4*)(g_eout + (size_t)r0 * HDIM + c8);
    uint4 pb = *(const uint4*)(g_eout + (size_t)r1 * HDIM + c8);
    float4 o0, o1;
    {
        __half2 a0 = *(__half2*)&pa.x, b0 = *(__half2*)&pb.x;
        __half2 a1 = *(__half2*)&pa.y, b1 = *(__half2*)&pb.y;
        o0.x = w0*__low2float(a0) + w1*__low2float(b0);
        o0.y = w0*__high2float(a0) + w1*__high2float(b0);
        o0.z = w0*__low2float(a1) + w1*__low2float(b1);
        o0.w = w0*__high2float(a1) + w1*__high2float(b1);
        __half2 a2 = *(__half2*)&pa.z, b2 = *(__half2*)&pb.z;
        __half2 a3 = *(__half2*)&pa.w, b3 = *(__half2*)&pb.w;
        o1.x = w0*__low2float(a2) + w1*__low2float(b2);
        o1.y = w0*__high2float(a2) + w1*__high2float(b2);
        o1.z = w0*__low2float(a3) + w1*__low2float(b3);
        o1.w = w0*__high2float(a3) + w1*__high2float(b3);
    }
    float* op = out + (size_t)tok * HDIM + c8;
    *(float4*)op = o0;
    *(float4*)(op + 4) = o1;
}

// ---------------- grouped GEMM: 128x128x32, 8 warps (64x32), 6-stage ring,
// ---------------- TWO stages per __syncthreads (prefetch distance 4) ----------------
#define BK 32
#define NSTG 6
#define LDA 40
#define LDB 136
#define STG_A (128*LDA*2)
#define STG_B (BK*LDB*2)
#define STG   (STG_A + STG_B)
#define SMEM_BYTES (NSTG*STG)

// MODE 1: A = g_xh gathered by token, B = g_w1h -> GELU -> g_hidden (fp16)
// MODE 2: A = g_hidden grouped rows,  B = g_w2h -> g_eout (fp16)
template<int KDIM, int NDIM, int MODE>
__global__ void __launch_bounds__(256, 2)
k_gemm_cp(int rtBase, int rtSpan)
{
    extern __shared__ char smem[];
    uint32_t sb = smem_u32(smem);

    int totalRT = g_tp[NEXP];
    int t = blockIdx.x;
    int rt = rtBase + t % rtSpan;
    int ct = t / rtSpan;
    if (rt >= totalRT) return;
    int e = 0;
    while (g_tp[e+1] <= rt) e++;
    int row0   = g_off[e] + (rt - g_tp[e]) * 128;
    int rowEnd = g_off[e+1];
    int n0 = ct * 128;

    const __half* Wh = ((MODE == 1) ? g_w1h : g_w2h) + (size_t)e * KDIM * NDIM;

    int tid = threadIdx.x, lane = tid & 31, wid = tid >> 5;
    int wm = wid >> 2, wn = wid & 3;   // 2x4 warps, each 64x32

    // ---- A loader: 2 threads/row, 32B each ----
    int lrowA = tid >> 1;
    int asub  = (tid & 1) * 16;
    int gr = row0 + lrowA;
    bool av = (gr < rowEnd);
    const __half* asrc;
    if (MODE == 1) asrc = g_xh     + (size_t)(av ? g_row_token[gr] : 0) * KDIM + asub;
    else           asrc = g_hidden + (size_t)(av ? gr : 0) * KDIM + asub;
    int asz = av ? 16 : 0;

    // ---- B loader: 8 threads/row, 32B each ----
    int lrowB = tid >> 3;
    int bsub  = (tid & 7) * 16;
    const __half* bsrc = Wh + (size_t)lrowB * NDIM + n0 + bsub;

    uint32_t aDst[2], bDst[2];
#pragma unroll
    for (int i = 0; i < 2; i++) {
        aDst[i] = sb + (uint32_t)((lrowA * LDA + asub + i * 8) * 2);
        bDst[i] = sb + STG_A + (uint32_t)((lrowB * LDB + bsub + i * 8) * 2);
    }

    float acc[4][4][4];
#pragma unroll
    for (int mi = 0; mi < 4; mi++)
#pragma unroll
        for (int ni = 0; ni < 4; ni++)
#pragma unroll
            for (int k = 0; k < 4; k++) acc[mi][ni][k] = 0.f;

    const int NKB = KDIM / BK;   // even (32 or 128)

#define ISSUE_A(c) do { \
        uint32_t so = ((c) % NSTG) * STG; \
        const __half* as_ = asrc + (c) * BK; \
        CPA16(aDst[0] + so, as_,     asz); \
        CPA16(aDst[1] + so, as_ + 8, asz); \
    } while(0)
#define ISSUE_B(c) do { \
        uint32_t so = ((c) % NSTG) * STG; \
        const __half* bs_ = bsrc + (size_t)(c) * BK * NDIM; \
        CPA16(bDst[0] + so, bs_,     16); \
        CPA16(bDst[1] + so, bs_ + 8, 16); \
    } while(0)

    // preload stages 0..3 (one commit group each); prefetch distance = 4
#pragma unroll
    for (int c = 0; c < 4; c++) { ISSUE_A(c); ISSUE_B(c); CPA_COMMIT(); }

    for (int kb = 0; kb < NKB; kb += 2) {
        CPA_WAIT2();          // stages kb, kb+1 resident (pending = kb+2, kb+3)
        __syncthreads();      // all warps past reads of stages (kb-2), (kb-1)

        bool pf = (kb + 4 < NKB);
#pragma unroll
        for (int kk = 0; kk < 4; kk++) {
            uint32_t abase = sb + ((kb + (kk >> 1)) % NSTG) * STG;
            uint32_t bbase = abase + STG_A;
            int k0 = (kk & 1) * 16;
            uint32_t afr[4][4];
#pragma unroll
            for (int mi = 0; mi < 4; mi++) {
                uint32_t addr = abase + (uint32_t)(((wm * 64 + mi * 16 + (lane & 15)) * LDA
                                                    + k0 + (lane >> 4) * 8) * 2);
                ldsm_x4(afr[mi][0], afr[mi][1], afr[mi][2], afr[mi][3], addr);
            }
            uint32_t bfr[4][2];
#pragma unroll
            for (int nb = 0; nb < 2; nb++) {
                uint32_t addr = bbase + (uint32_t)(((k0 + (lane & 15)) * LDB
                                                    + wn * 32 + nb * 16 + (lane >> 4) * 8) * 2);
                uint32_t r0, r1, r2, r3;
                ldsm_x4t(r0, r1, r2, r3, addr);
                bfr[nb*2][0] = r0;   bfr[nb*2][1] = r1;
                bfr[nb*2+1][0] = r2; bfr[nb*2+1][1] = r3;
            }
            if (pf) {
                if (kk == 0) ISSUE_A(kb + 4);
                if (kk == 1) ISSUE_B(kb + 4);
                if (kk == 2) ISSUE_A(kb + 5);
                if (kk == 3) ISSUE_B(kb + 5);
            }
            if (kk == 1) CPA_COMMIT();
#pragma unroll
            for (int mi = 0; mi < 4; mi++)
#pragma unroll
                for (int ni = 0; ni < 4; ni++)
                    mma16816(acc[mi][ni], afr[mi], bfr[ni]);
        }
        CPA_COMMIT();
    }
#undef ISSUE_A
#undef ISSUE_B

    // ---- epilogue ----
    int mrow = row0 + wm * 64 + (lane >> 2);
    int ncol = n0 + wn * 32 + (lane & 3) * 2;
#pragma unroll
    for (int mi = 0; mi < 4; mi++) {
#pragma unroll
        for (int ni = 0; ni < 4; ni++) {
            int r0r = mrow + mi * 16;
            int c   = ncol + ni * 8;
            if (MODE == 1) {
                if (r0r < rowEnd) {
                    __half2 h = __floats2half2_rn(gelu_exact(acc[mi][ni][0]),
                                                  gelu_exact(acc[mi][ni][1]));
                    *(__half2*)&g_hidden[(size_t)r0r * NDIM + c] = h;
                }
                if (r0r + 8 < rowEnd) {
                    __half2 h = __floats2half2_rn(gelu_exact(acc[mi][ni][2]),
                                                  gelu_exact(acc[mi][ni][3]));
                    *(__half2*)&g_hidden[(size_t)(r0r + 8) * NDIM + c] = h;
                }
            } else {
                if (r0r < rowEnd) {
                    __half2 h = __floats2half2_rn(acc[mi][ni][0], acc[mi][ni][1]);
                    *(__half2*)&g_eout[(size_t)r0r * NDIM + c] = h;
                }
                if (r0r + 8 < rowEnd) {
                    __half2 h = __floats2half2_rn(acc[mi][ni][2], acc[mi][ni][3]);
                    *(__half2*)&g_eout[(size_t)(r0r + 8) * NDIM + c] = h;
                }
            }
        }
    }
}

// ---------------- launch ----------------
extern "C" void kernel_launch(void* const* d_in, const int* in_sizes, int n_in,
                              void* d_out, int out_size) {
    const float* x  = (const float*)d_in[0];
    const float* rw = (const float*)d_in[1];
    const float* rb = (const float*)d_in[2];
    const float* w1 = (const float*)d_in[3];
    const float* w2 = (const float*)d_in[4];
    float* out = (float*)d_out;

    static cudaStream_t s1 = nullptr;
    static cudaEvent_t evF = nullptr, evW1 = nullptr, evRT = nullptr,
                       evW2 = nullptr, evG2B = nullptr;
    static bool init_done = false;
    if (!init_done) {
        cudaFuncSetAttribute((const void*)k_gemm_cp<HDIM, FDIM, 1>,
                             cudaFuncAttributeMaxDynamicSharedMemorySize, SMEM_BYTES);
        cudaFuncSetAttribute((const void*)k_gemm_cp<FDIM, HDIM, 2>,
                             cudaFuncAttributeMaxDynamicSharedMemorySize, SMEM_BYTES);
        cudaStreamCreateWithFlags(&s1, cudaStreamNonBlocking);
        cudaEventCreateWithFlags(&evF,   cudaEventDisableTiming);
        cudaEventCreateWithFlags(&evW1,  cudaEventDisableTiming);
        cudaEventCreateWithFlags(&evRT,  cudaEventDisableTiming);
        cudaEventCreateWithFlags(&evW2,  cudaEventDisableTiming);
        cudaEventCreateWithFlags(&evG2B, cudaEventDisableTiming);
        init_done = true;
    }

    __half *xh_p, *w1h_p, *w2h_p;
    cudaGetSymbolAddress((void**)&xh_p,  g_xh);
    cudaGetSymbolAddress((void**)&w1h_p, g_w1h);
    cudaGetSymbolAddress((void**)&w2h_p, g_w2h);

    // fork
    cudaEventRecord(evF, 0);
    cudaStreamWaitEvent(s1, evF, 0);

    // side stream s1: init, router (fused x-convert + offsets + scatter), w2 convert
    k_init0<<<1, 32, 0, s1>>>();
    k_router<<<NTOK/8, 256, 0, s1>>>((const float4*)x, (const float4*)rw, rb, (uint2*)xh_p);
    cudaEventRecord(evRT, s1);
    k_convert_w2<<<2048, 256, 0, s1>>>((const float4*)w2, (uint2*)w2h_p);
    cudaEventRecord(evW2, s1);

    // main stream: w1 conversion, then half A of both GEMMs
    k_convert_w1<<<4096, 256>>>((const float4*)w1, (uint2*)w1h_p);
    cudaEventRecord(evW1, 0);

    cudaStreamWaitEvent(0, evRT, 0);
    k_gemm_cp<HDIM, FDIM, 1><<<HALF_RT*(FDIM/128), 256, SMEM_BYTES>>>(0, HALF_RT);
    cudaStreamWaitEvent(s1, evW1, 0);
    k_gemm_cp<HDIM, FDIM, 1><<<HALF_RT*(FDIM/128), 256, SMEM_BYTES, s1>>>(HALF_RT, HALF_RT);

    cudaStreamWaitEvent(0, evW2, 0);
    k_gemm_cp<FDIM, HDIM, 2><<<HALF_RT*(HDIM/128), 256, SMEM_BYTES>>>(0, HALF_RT);
    k_gemm_cp<FDIM, HDIM, 2><<<HALF_RT*(HDIM/128), 256, SMEM_BYTES, s1>>>(HALF_RT, HALF_RT);
    cudaEventRecord(evG2B, s1);

    cudaStreamWaitEvent(0, evG2B, 0);
    k_combine<<<(NTOK*HDIM/8 + 255)/256, 256>>>(out);
}

// round 16
// speedup vs baseline: 1.0440x; 1.0440x over previous
#include <cuda_runtime.h>
#include <cuda_fp16.h>
#include <cstdint>
#include <math.h>

#define NTOK 8192
#define HDIM 1024
#define FDIM 4096
#define NEXP 8
#define NROWS (NTOK*2)
#define HALF_RT 68

// ---------------- device scratch (allocation-free) ----------------
__device__ int    g_cnt[NEXP];
__device__ int    g_fill[NEXP];
__device__ int    g_off[NEXP+1];
__device__ int    g_tp[NEXP+1];
__device__ int    g_done;
__device__ int    g_tok_e[NTOK*2];
__device__ float  g_tok_w[NTOK*2];
__device__ int    g_pos[NTOK*2];
__device__ int    g_row_token[NROWS];
__device__ __half g_hidden[(size_t)NROWS*FDIM];   // grouped hidden (fp16)
__device__ __half g_xh[(size_t)NTOK*HDIM];        // x fp16 (written by router)
__device__ __half g_w1h[(size_t)NEXP*HDIM*FDIM];  // w1 fp16 [e][H][F]
__device__ __half g_w2h[(size_t)NEXP*FDIM*HDIM];  // w2 fp16 [e][F][H]
__device__ __half g_eout[(size_t)NROWS*HDIM];     // per-row GEMM2 out fp16

// ---------------- helpers ----------------
__device__ __forceinline__ uint32_t smem_u32(const void* p) {
    uint32_t a;
    asm("{ .reg .u64 t; cvta.to.shared.u64 t, %1; cvt.u32.u64 %0, t; }" : "=r"(a) : "l"(p));
    return a;
}
#define CPA16(dst,src,sz) asm volatile("cp.async.cg.shared.global [%0],[%1],16,%2;" :: "r"(dst), "l"(src), "r"(sz))
#define CPA_COMMIT() asm volatile("cp.async.commit_group;" ::: "memory")
#define CPA_WAIT2()  asm volatile("cp.async.wait_group 2;" ::: "memory")

__device__ __forceinline__ void ldsm_x4(uint32_t& r0, uint32_t& r1, uint32_t& r2, uint32_t& r3, uint32_t a) {
    asm volatile("ldmatrix.sync.aligned.m8n8.x4.shared.b16 {%0,%1,%2,%3},[%4];"
                 : "=r"(r0), "=r"(r1), "=r"(r2), "=r"(r3) : "r"(a));
}
__device__ __forceinline__ void ldsm_x4t(uint32_t& r0, uint32_t& r1, uint32_t& r2, uint32_t& r3, uint32_t a) {
    asm volatile("ldmatrix.sync.aligned.m8n8.x4.trans.shared.b16 {%0,%1,%2,%3},[%4];"
                 : "=r"(r0), "=r"(r1), "=r"(r2), "=r"(r3) : "r"(a));
}
__device__ __forceinline__ void mma16816(float* c, const uint32_t* a, const uint32_t* b) {
    asm volatile("mma.sync.aligned.m16n8k16.row.col.f32.f16.f16.f32 "
                 "{%0,%1,%2,%3},{%4,%5,%6,%7},{%8,%9},{%0,%1,%2,%3};"
                 : "+f"(c[0]), "+f"(c[1]), "+f"(c[2]), "+f"(c[3])
                 : "r"(a[0]), "r"(a[1]), "r"(a[2]), "r"(a[3]), "r"(b[0]), "r"(b[1]));
}
__device__ __forceinline__ float gelu_exact(float v) {
    return 0.5f * v * (1.f + erff(v * 0.70710678118654752f));
}

// ---------------- small kernels ----------------
__global__ void k_init0() {
    int i = threadIdx.x;
    if (i < NEXP) { g_cnt[i] = 0; g_fill[i] = 0; }
    if (i == 0) g_done = 0;
}
__global__ void k_convert_w1(const float4* __restrict__ w1, uint2* __restrict__ w1h) {
    const int NW = NEXP*HDIM*FDIM/4;
    for (int i = blockIdx.x * blockDim.x + threadIdx.x; i < NW; i += gridDim.x * blockDim.x) {
        float4 v = w1[i];
        __half2 a = __floats2half2_rn(v.x, v.y);
        __half2 b = __floats2half2_rn(v.z, v.w);
        w1h[i] = make_uint2(*(uint32_t*)&a, *(uint32_t*)&b);
    }
}
__global__ void k_convert_w2(const float4* __restrict__ w2, uint2* __restrict__ w2h) {
    const int NW = NEXP*HDIM*FDIM/4;
    for (int i = blockIdx.x * blockDim.x + threadIdx.x; i < NW; i += gridDim.x * blockDim.x) {
        float4 v = w2[i];
        __half2 a = __floats2half2_rn(v.x, v.y);
        __half2 b = __floats2half2_rn(v.z, v.w);
        w2h[i] = make_uint2(*(uint32_t*)&a, *(uint32_t*)&b);
    }
}

// router: top-2 selection + fused x->fp16 conversion + fused offsets
__global__ void k_router(const float4* __restrict__ x4,
                         const float4* __restrict__ rw4,
                         const float* __restrict__ rb,
                         uint2* __restrict__ xh2) {
    int warp = (blockIdx.x * blockDim.x + threadIdx.x) >> 5;
    int lane = threadIdx.x & 31;
    if (warp < NTOK) {
        const int Q = HDIM / 4;          // 256 float4 per row
        float acc[NEXP];
#pragma unroll
        for (int e = 0; e < NEXP; e++) acc[e] = 0.f;
#pragma unroll
        for (int j = 0; j < Q / 32; j++) {
            int idx = j * 32 + lane;
            float4 v = __ldg(x4 + (size_t)warp * Q + idx);
#pragma unroll
            for (int e = 0; e < NEXP; e++) {
                float4 w = __ldg(rw4 + (size_t)e * Q + idx);
                acc[e] = fmaf(v.x, w.x, acc[e]);
                acc[e] = fmaf(v.y, w.y, acc[e]);
                acc[e] = fmaf(v.z, w.z, acc[e]);
                acc[e] = fmaf(v.w, w.w, acc[e]);
            }
            // fused x -> fp16 store
            __half2 a = __floats2half2_rn(v.x, v.y);
            __half2 b = __floats2half2_rn(v.z, v.w);
            xh2[(size_t)warp * Q + idx] = make_uint2(*(uint32_t*)&a, *(uint32_t*)&b);
        }
#pragma unroll
        for (int o = 16; o > 0; o >>= 1)
#pragma unroll
            for (int e = 0; e < NEXP; e++)
                acc[e] += __shfl_xor_sync(0xffffffffu, acc[e], o);
        if (lane == 0) {
            float l[NEXP];
#pragma unroll
            for (int e = 0; e < NEXP; e++) l[e] = acc[e] + rb[e];
            int i0 = 0; float b0 = l[0];
#pragma unroll
            for (int e = 1; e < NEXP; e++) if (l[e] > b0) { b0 = l[e]; i0 = e; }
            int i1 = (i0 == 0) ? 1 : 0; float b1 = -3.4e38f;
#pragma unroll
            for (int e = 0; e < NEXP; e++)
                if (e != i0 && l[e] > b1) { b1 = l[e]; i1 = e; }
            float w0 = 1.f / (1.f + expf(b1 - b0));
            g_tok_e[warp*2]   = i0;  g_tok_e[warp*2+1] = i1;
            g_tok_w[warp*2]   = w0;  g_tok_w[warp*2+1] = 1.f - w0;
            atomicAdd(&g_cnt[i0], 1);
            atomicAdd(&g_cnt[i1], 1);
        }
    }
    __syncthreads();
    if (threadIdx.x == 0) {
        __threadfence();
        int prev = atomicAdd(&g_done, 1);
        if (prev == gridDim.x - 1) {
            g_off[0] = 0; g_tp[0] = 0;
            for (int e = 0; e < NEXP; e++) {
                g_off[e+1] = g_off[e] + g_cnt[e];
                g_tp[e+1]  = g_tp[e]  + (g_cnt[e] + 127) / 128;
            }
            __threadfence();
        }
    }
}
__global__ void k_scatter() {
    int i = blockIdx.x * blockDim.x + threadIdx.x;
    if (i >= NTOK * 2) return;
    int e = g_tok_e[i];
    int r = g_off[e] + atomicAdd(&g_fill[e], 1);
    g_row_token[r] = i >> 1;
    g_pos[i] = r;
}
// combine: out[tok] = w0*eout[r0] + w1*eout[r1], 8 elems per thread
__global__ void k_combine(float* __restrict__ out) {
    int idx = blockIdx.x * blockDim.x + threadIdx.x;
    if (idx >= NTOK * HDIM / 8) return;
    int tok = idx / (HDIM / 8);
    int c8  = (idx % (HDIM / 8)) * 8;
    float w0 = g_tok_w[tok*2], w1 = g_tok_w[tok*2+1];
    int   r0 = g_pos[tok*2],  r1 = g_pos[tok*2+1];
    uint4 pa = *(const uint4*)(g_eout + (size_t)r0 * HDIM + c8);
    uint4 pb = *(const uint4*)(g_eout + (size_t)r1 * HDIM + c8);
    float4 o0, o1;
    {
        __half2 a0 = *(__half2*)&pa.x, b0 = *(__half2*)&pb.x;
        __half2 a1 = *(__half2*)&pa.y, b1 = *(__half2*)&pb.y;
        o0.x = w0*__low2float(a0) + w1*__low2float(b0);
        o0.y = w0*__high2float(a0) + w1*__high2float(b0);
        o0.z = w0*__low2float(a1) + w1*__low2float(b1);
        o0.w = w0*__high2float(a1) + w1*__high2float(b1);
        __half2 a2 = *(__half2*)&pa.z, b2 = *(__half2*)&pb.z;
        __half2 a3 = *(__half2*)&pa.w, b3 = *(__half2*)&pb.w;
        o1.x = w0*__low2float(a2) + w1*__low2float(b2);
        o1.y = w0*__high2float(a2) + w1*__high2float(b2);
        o1.z = w0*__low2float(a3) + w1*__low2float(b3);
        o1.w = w0*__high2float(a3) + w1*__high2float(b3);
    }
    float* op = out + (size_t)tok * HDIM + c8;
    *(float4*)op = o0;
    *(float4*)(op + 4) = o1;
}

// ---------------- grouped GEMM: 128x128x32, 8 warps (64x32), 6-stage ring,
// ---------------- TWO stages per __syncthreads (prefetch distance 4) ----------------
#define BK 32
#define NSTG 6
#define LDA 40
#define LDB 136
#define STG_A (128*LDA*2)
#define STG_B (BK*LDB*2)
#define STG   (STG_A + STG_B)
#define SMEM_BYTES (NSTG*STG)

// MODE 1: A = g_xh gathered by token, B = g_w1h -> GELU -> g_hidden (fp16)
// MODE 2: A = g_hidden grouped rows,  B = g_w2h -> g_eout (fp16)
template<int KDIM, int NDIM, int MODE>
__global__ void __launch_bounds__(256, 2)
k_gemm_cp(int rtBase, int rtSpan)
{
    extern __shared__ char smem[];
    uint32_t sb = smem_u32(smem);

    int totalRT = g_tp[NEXP];
    int t = blockIdx.x;
    int rt = rtBase + t % rtSpan;
    int ct = t / rtSpan;
    if (rt >= totalRT) return;
    int e = 0;
    while (g_tp[e+1] <= rt) e++;
    int row0   = g_off[e] + (rt - g_tp[e]) * 128;
    int rowEnd = g_off[e+1];
    int n0 = ct * 128;

    const __half* Wh = ((MODE == 1) ? g_w1h : g_w2h) + (size_t)e * KDIM * NDIM;

    int tid = threadIdx.x, lane = tid & 31, wid = tid >> 5;
    int wm = wid >> 2, wn = wid & 3;   // 2x4 warps, each 64x32

    // ---- A loader: 2 threads/row, 32B each ----
    int lrowA = tid >> 1;
    int asub  = (tid & 1) * 16;
    int gr = row0 + lrowA;
    bool av = (gr < rowEnd);
    const __half* asrc;
    if (MODE == 1) asrc = g_xh     + (size_t)(av ? g_row_token[gr] : 0) * KDIM + asub;
    else           asrc = g_hidden + (size_t)(av ? gr : 0) * KDIM + asub;
    int asz = av ? 16 : 0;

    // ---- B loader: 8 threads/row, 32B each ----
    int lrowB = tid >> 3;
    int bsub  = (tid & 7) * 16;
    const __half* bsrc = Wh + (size_t)lrowB * NDIM + n0 + bsub;

    uint32_t aDst[2], bDst[2];
#pragma unroll
    for (int i = 0; i < 2; i++) {
        aDst[i] = sb + (uint32_t)((lrowA * LDA + asub + i * 8) * 2);
        bDst[i] = sb + STG_A + (uint32_t)((lrowB * LDB + bsub + i * 8) * 2);
    }

    float acc[4][4][4];
#pragma unroll
    for (int mi = 0; mi < 4; mi++)
#pragma unroll
        for (int ni = 0; ni < 4; ni++)
#pragma unroll
            for (int k = 0; k < 4; k++) acc[mi][ni][k] = 0.f;

    const int NKB = KDIM / BK;   // even (32 or 128)

#define ISSUE_A(c) do { \
        uint32_t so = ((c) % NSTG) * STG; \
        const __half* as_ = asrc + (c) * BK; \
        CPA16(aDst[0] + so, as_,     asz); \
        CPA16(aDst[1] + so, as_ + 8, asz); \
    } while(0)
#define ISSUE_B(c) do { \
        uint32_t so = ((c) % NSTG) * STG; \
        const __half* bs_ = bsrc + (size_t)(c) * BK * NDIM; \
        CPA16(bDst[0] + so, bs_,     16); \
        CPA16(bDst[1] + so, bs_ + 8, 16); \
    } while(0)

    // preload stages 0..3 (one commit group each); prefetch distance = 4
#pragma unroll
    for (int c = 0; c < 4; c++) { ISSUE_A(c); ISSUE_B(c); CPA_COMMIT(); }

    for (int kb = 0; kb < NKB; kb += 2) {
        CPA_WAIT2();          // stages kb, kb+1 resident (pending = kb+2, kb+3)
        __syncthreads();      // all warps past reads of stages (kb-2), (kb-1)

        bool pf = (kb + 4 < NKB);
#pragma unroll
        for (int kk = 0; kk < 4; kk++) {
            uint32_t abase = sb + ((kb + (kk >> 1)) % NSTG) * STG;
            uint32_t bbase = abase + STG_A;
            int k0 = (kk & 1) * 16;
            uint32_t afr[4][4];
#pragma unroll
            for (int mi = 0; mi < 4; mi++) {
                uint32_t addr = abase + (uint32_t)(((wm * 64 + mi * 16 + (lane & 15)) * LDA
                                                    + k0 + (lane >> 4) * 8) * 2);
                ldsm_x4(afr[mi][0], afr[mi][1], afr[mi][2], afr[mi][3], addr);
            }
            uint32_t bfr[4][2];
#pragma unroll
            for (int nb = 0; nb < 2; nb++) {
                uint32_t addr = bbase + (uint32_t)(((k0 + (lane & 15)) * LDB
                                                    + wn * 32 + nb * 16 + (lane >> 4) * 8) * 2);
                uint32_t r0, r1, r2, r3;
                ldsm_x4t(r0, r1, r2, r3, addr);
                bfr[nb*2][0] = r0;   bfr[nb*2][1] = r1;
                bfr[nb*2+1][0] = r2; bfr[nb*2+1][1] = r3;
            }
            if (pf) {
                if (kk == 0) ISSUE_A(kb + 4);
                if (kk == 1) ISSUE_B(kb + 4);
                if (kk == 2) ISSUE_A(kb + 5);
                if (kk == 3) ISSUE_B(kb + 5);
            }
            if (kk == 1) CPA_COMMIT();
#pragma unroll
            for (int mi = 0; mi < 4; mi++)
#pragma unroll
                for (int ni = 0; ni < 4; ni++)
                    mma16816(acc[mi][ni], afr[mi], bfr[ni]);
        }
        CPA_COMMIT();
    }
#undef ISSUE_A
#undef ISSUE_B

    // ---- epilogue ----
    int mrow = row0 + wm * 64 + (lane >> 2);
    int ncol = n0 + wn * 32 + (lane & 3) * 2;
#pragma unroll
    for (int mi = 0; mi < 4; mi++) {
#pragma unroll
        for (int ni = 0; ni < 4; ni++) {
            int r0r = mrow + mi * 16;
            int c   = ncol + ni * 8;
            if (MODE == 1) {
                if (r0r < rowEnd) {
                    __half2 h = __floats2half2_rn(gelu_exact(acc[mi][ni][0]),
                                                  gelu_exact(acc[mi][ni][1]));
                    *(__half2*)&g_hidden[(size_t)r0r * NDIM + c] = h;
                }
                if (r0r + 8 < rowEnd) {
                    __half2 h = __floats2half2_rn(gelu_exact(acc[mi][ni][2]),
                                                  gelu_exact(acc[mi][ni][3]));
                    *(__half2*)&g_hidden[(size_t)(r0r + 8) * NDIM + c] = h;
                }
            } else {
                if (r0r < rowEnd) {
                    __half2 h = __floats2half2_rn(acc[mi][ni][0], acc[mi][ni][1]);
                    *(__half2*)&g_eout[(size_t)r0r * NDIM + c] = h;
                }
                if (r0r + 8 < rowEnd) {
                    __half2 h = __floats2half2_rn(acc[mi][ni][2], acc[mi][ni][3]);
                    *(__half2*)&g_eout[(size_t)(r0r + 8) * NDIM + c] = h;
                }
            }
        }
    }
}

// ---------------- launch ----------------
extern "C" void kernel_launch(void* const* d_in, const int* in_sizes, int n_in,
                              void* d_out, int out_size) {
    const float* x  = (const float*)d_in[0];
    const float* rw = (const float*)d_in[1];
    const float* rb = (const float*)d_in[2];
    const float* w1 = (const float*)d_in[3];
    const float* w2 = (const float*)d_in[4];
    float* out = (float*)d_out;

    static cudaStream_t s1 = nullptr;
    static cudaEvent_t evF = nullptr, evW1 = nullptr, evRT = nullptr,
                       evW2 = nullptr, evG2B = nullptr;
    static bool init_done = false;
    if (!init_done) {
        cudaFuncSetAttribute((const void*)k_gemm_cp<HDIM, FDIM, 1>,
                             cudaFuncAttributeMaxDynamicSharedMemorySize, SMEM_BYTES);
        cudaFuncSetAttribute((const void*)k_gemm_cp<FDIM, HDIM, 2>,
                             cudaFuncAttributeMaxDynamicSharedMemorySize, SMEM_BYTES);
        cudaStreamCreateWithFlags(&s1, cudaStreamNonBlocking);
        cudaEventCreateWithFlags(&evF,   cudaEventDisableTiming);
        cudaEventCreateWithFlags(&evW1,  cudaEventDisableTiming);
        cudaEventCreateWithFlags(&evRT,  cudaEventDisableTiming);
        cudaEventCreateWithFlags(&evW2,  cudaEventDisableTiming);
        cudaEventCreateWithFlags(&evG2B, cudaEventDisableTiming);
        init_done = true;
    }

    __half *xh_p, *w1h_p, *w2h_p;
    cudaGetSymbolAddress((void**)&xh_p,  g_xh);
    cudaGetSymbolAddress((void**)&w1h_p, g_w1h);
    cudaGetSymbolAddress((void**)&w2h_p, g_w2h);

    // fork
    cudaEventRecord(evF, 0);
    cudaStreamWaitEvent(s1, evF, 0);

    // side stream s1: routing metadata (+x conversion fused) + w2 conversion
    k_init0<<<1, 32, 0, s1>>>();
    k_router<<<NTOK/8, 256, 0, s1>>>((const float4*)x, (const float4*)rw, rb, (uint2*)xh_p);
    k_scatter<<<(NTOK*2 + 255)/256, 256, 0, s1>>>();
    cudaEventRecord(evRT, s1);
    k_convert_w2<<<2048, 256, 0, s1>>>((const float4*)w2, (uint2*)w2h_p);
    cudaEventRecord(evW2, s1);

    // main stream: w1 conversion, then half A of both GEMMs
    k_convert_w1<<<4096, 256>>>((const float4*)w1, (uint2*)w1h_p);
    cudaEventRecord(evW1, 0);

    cudaStreamWaitEvent(0, evRT, 0);
    k_gemm_cp<HDIM, FDIM, 1><<<HALF_RT*(FDIM/128), 256, SMEM_BYTES>>>(0, HALF_RT);
    cudaStreamWaitEvent(s1, evW1, 0);
    k_gemm_cp<HDIM, FDIM, 1><<<HALF_RT*(FDIM/128), 256, SMEM_BYTES, s1>>>(HALF_RT, HALF_RT);

    cudaStreamWaitEvent(0, evW2, 0);
    k_gemm_cp<FDIM, HDIM, 2><<<HALF_RT*(HDIM/128), 256, SMEM_BYTES>>>(0, HALF_RT);
    k_gemm_cp<FDIM, HDIM, 2><<<HALF_RT*(HDIM/128), 256, SMEM_BYTES, s1>>>(HALF_RT, HALF_RT);
    cudaEventRecord(evG2B, s1);

    cudaStreamWaitEvent(0, evG2B, 0);
    k_combine<<<(NTOK*HDIM/8 + 255)/256, 256>>>(out);
}

// round 17
// speedup vs baseline: 1.0483x; 1.0041x over previous
#include <cuda_runtime.h>
#include <cuda_fp16.h>
#include <cstdint>
#include <math.h>

#define NTOK 8192
#define HDIM 1024
#define FDIM 4096
#define NEXP 8
#define NROWS (NTOK*2)
#define HALF_RT 68

// ---------------- device scratch (allocation-free) ----------------
__device__ int    g_cnt[NEXP];
__device__ int    g_fill[NEXP];
__device__ int    g_off[NEXP+1];
__device__ int    g_tp[NEXP+1];
__device__ int    g_done;
__device__ int    g_tok_e[NTOK*2];
__device__ float  g_tok_w[NTOK*2];
__device__ int    g_pos[NTOK*2];
__device__ int    g_row_token[NROWS];
__device__ __half g_hidden[(size_t)NROWS*FDIM];   // grouped hidden (fp16)
__device__ __half g_xh[(size_t)NTOK*HDIM];        // x fp16 (written by router)
__device__ __half g_w1h[(size_t)NEXP*HDIM*FDIM];  // w1 fp16 [e][H][F]
__device__ __half g_w2h[(size_t)NEXP*FDIM*HDIM];  // w2 fp16 [e][F][H]
__device__ __half g_eout[(size_t)NROWS*HDIM];     // per-row GEMM2 out fp16

// ---------------- helpers ----------------
__device__ __forceinline__ uint32_t smem_u32(const void* p) {
    uint32_t a;
    asm("{ .reg .u64 t; cvta.to.shared.u64 t, %1; cvt.u32.u64 %0, t; }" : "=r"(a) : "l"(p));
    return a;
}
#define CPA16(dst,src,sz) asm volatile("cp.async.cg.shared.global [%0],[%1],16,%2;" :: "r"(dst), "l"(src), "r"(sz))
#define CPA_COMMIT() asm volatile("cp.async.commit_group;" ::: "memory")
#define CPA_WAIT2()  asm volatile("cp.async.wait_group 2;" ::: "memory")

__device__ __forceinline__ void ldsm_x4(uint32_t& r0, uint32_t& r1, uint32_t& r2, uint32_t& r3, uint32_t a) {
    asm volatile("ldmatrix.sync.aligned.m8n8.x4.shared.b16 {%0,%1,%2,%3},[%4];"
                 : "=r"(r0), "=r"(r1), "=r"(r2), "=r"(r3) : "r"(a));
}
__device__ __forceinline__ void ldsm_x4t(uint32_t& r0, uint32_t& r1, uint32_t& r2, uint32_t& r3, uint32_t a) {
    asm volatile("ldmatrix.sync.aligned.m8n8.x4.trans.shared.b16 {%0,%1,%2,%3},[%4];"
                 : "=r"(r0), "=r"(r1), "=r"(r2), "=r"(r3) : "r"(a));
}
__device__ __forceinline__ void mma16816(float* c, const uint32_t* a, const uint32_t* b) {
    asm volatile("mma.sync.aligned.m16n8k16.row.col.f32.f16.f16.f32 "
                 "{%0,%1,%2,%3},{%4,%5,%6,%7},{%8,%9},{%0,%1,%2,%3};"
                 : "+f"(c[0]), "+f"(c[1]), "+f"(c[2]), "+f"(c[3])
                 : "r"(a[0]), "r"(a[1]), "r"(a[2]), "r"(a[3]), "r"(b[0]), "r"(b[1]));
}
__device__ __forceinline__ float gelu_exact(float v) {
    return 0.5f * v * (1.f + erff(v * 0.70710678118654752f));
}

// ---------------- small kernels ----------------
__global__ void k_init0() {
    int i = threadIdx.x;
    if (i < NEXP) { g_cnt[i] = 0; g_fill[i] = 0; }
    if (i == 0) g_done = 0;
}
__global__ void k_convert_w1(const float4* __restrict__ w1, uint2* __restrict__ w1h) {
    const int NW = NEXP*HDIM*FDIM/4;
    for (int i = blockIdx.x * blockDim.x + threadIdx.x; i < NW; i += gridDim.x * blockDim.x) {
        float4 v = w1[i];
        __half2 a = __floats2half2_rn(v.x, v.y);
        __half2 b = __floats2half2_rn(v.z, v.w);
        w1h[i] = make_uint2(*(uint32_t*)&a, *(uint32_t*)&b);
    }
}
__global__ void k_convert_w2(const float4* __restrict__ w2, uint2* __restrict__ w2h) {
    const int NW = NEXP*HDIM*FDIM/4;
    for (int i = blockIdx.x * blockDim.x + threadIdx.x; i < NW; i += gridDim.x * blockDim.x) {
        float4 v = w2[i];
        __half2 a = __floats2half2_rn(v.x, v.y);
        __half2 b = __floats2half2_rn(v.z, v.w);
        w2h[i] = make_uint2(*(uint32_t*)&a, *(uint32_t*)&b);
    }
}

// router: top-2 selection + fused x->fp16 conversion + fused offsets
__global__ void k_router(const float4* __restrict__ x4,
                         const float4* __restrict__ rw4,
                         const float* __restrict__ rb,
                         uint2* __restrict__ xh2) {
    int warp = (blockIdx.x * blockDim.x + threadIdx.x) >> 5;
    int lane = threadIdx.x & 31;
    if (warp < NTOK) {
        const int Q = HDIM / 4;          // 256 float4 per row
        float acc[NEXP];
#pragma unroll
        for (int e = 0; e < NEXP; e++) acc[e] = 0.f;
#pragma unroll
        for (int j = 0; j < Q / 32; j++) {
            int idx = j * 32 + lane;
            float4 v = __ldg(x4 + (size_t)warp * Q + idx);
#pragma unroll
            for (int e = 0; e < NEXP; e++) {
                float4 w = __ldg(rw4 + (size_t)e * Q + idx);
                acc[e] = fmaf(v.x, w.x, acc[e]);
                acc[e] = fmaf(v.y, w.y, acc[e]);
                acc[e] = fmaf(v.z, w.z, acc[e]);
                acc[e] = fmaf(v.w, w.w, acc[e]);
            }
            // fused x -> fp16 store
            __half2 a = __floats2half2_rn(v.x, v.y);
            __half2 b = __floats2half2_rn(v.z, v.w);
            xh2[(size_t)warp * Q + idx] = make_uint2(*(uint32_t*)&a, *(uint32_t*)&b);
        }
#pragma unroll
        for (int o = 16; o > 0; o >>= 1)
#pragma unroll
            for (int e = 0; e < NEXP; e++)
                acc[e] += __shfl_xor_sync(0xffffffffu, acc[e], o);
        if (lane == 0) {
            float l[NEXP];
#pragma unroll
            for (int e = 0; e < NEXP; e++) l[e] = acc[e] + rb[e];
            int i0 = 0; float b0 = l[0];
#pragma unroll
            for (int e = 1; e < NEXP; e++) if (l[e] > b0) { b0 = l[e]; i0 = e; }
            int i1 = (i0 == 0) ? 1 : 0; float b1 = -3.4e38f;
#pragma unroll
            for (int e = 0; e < NEXP; e++)
                if (e != i0 && l[e] > b1) { b1 = l[e]; i1 = e; }
            float w0 = 1.f / (1.f + expf(b1 - b0));
            g_tok_e[warp*2]   = i0;  g_tok_e[warp*2+1] = i1;
            g_tok_w[warp*2]   = w0;  g_tok_w[warp*2+1] = 1.f - w0;
            atomicAdd(&g_cnt[i0], 1);
            atomicAdd(&g_cnt[i1], 1);
        }
    }
    __syncthreads();
    if (threadIdx.x == 0) {
        __threadfence();
        int prev = atomicAdd(&g_done, 1);
        if (prev == gridDim.x - 1) {
            g_off[0] = 0; g_tp[0] = 0;
            for (int e = 0; e < NEXP; e++) {
                g_off[e+1] = g_off[e] + g_cnt[e];
                g_tp[e+1]  = g_tp[e]  + (g_cnt[e] + 127) / 128;
            }
            __threadfence();
        }
    }
}
__global__ void k_scatter() {
    int i = blockIdx.x * blockDim.x + threadIdx.x;
    if (i >= NTOK * 2) return;
    int e = g_tok_e[i];
    int r = g_off[e] + atomicAdd(&g_fill[e], 1);
    g_row_token[r] = i >> 1;
    g_pos[i] = r;
}
// combine: out[tok] = w0*eout[r0] + w1*eout[r1], 8 elems per thread
__global__ void k_combine(float* __restrict__ out) {
    int idx = blockIdx.x * blockDim.x + threadIdx.x;
    if (idx >= NTOK * HDIM / 8) return;
    int tok = idx / (HDIM / 8);
    int c8  = (idx % (HDIM / 8)) * 8;
    float w0 = g_tok_w[tok*2], w1 = g_tok_w[tok*2+1];
    int   r0 = g_pos[tok*2],  r1 = g_pos[tok*2+1];
    uint4 pa = *(const uint4*)(g_eout + (size_t)r0 * HDIM + c8);
    uint4 pb = *(const uint4*)(g_eout + (size_t)r1 * HDIM + c8);
    float4 o0, o1;
    {
        __half2 a0 = *(__half2*)&pa.x, b0 = *(__half2*)&pb.x;
        __half2 a1 = *(__half2*)&pa.y, b1 = *(__half2*)&pb.y;
        o0.x = w0*__low2float(a0) + w1*__low2float(b0);
        o0.y = w0*__high2float(a0) + w1*__high2float(b0);
        o0.z = w0*__low2float(a1) + w1*__low2float(b1);
        o0.w = w0*__high2float(a1) + w1*__high2float(b1);
        __half2 a2 = *(__half2*)&pa.z, b2 = *(__half2*)&pb.z;
        __half2 a3 = *(__half2*)&pa.w, b3 = *(__half2*)&pb.w;
        o1.x = w0*__low2float(a2) + w1*__low2float(b2);
        o1.y = w0*__high2float(a2) + w1*__high2float(b2);
        o1.z = w0*__low2float(a3) + w1*__low2float(b3);
        o1.w = w0*__high2float(a3) + w1*__high2float(b3);
    }
    float* op = out + (size_t)tok * HDIM + c8;
    *(float4*)op = o0;
    *(float4*)(op + 4) = o1;
}

// ---------------- grouped GEMM: 128x128x32, 8 warps (64x32), 6-stage ring,
// ---------------- TWO stages per __syncthreads (prefetch distance 4) ----------------
#define BK 32
#define NSTG 6
#define LDA 40
#define LDB 136
#define STG_A (128*LDA*2)
#define STG_B (BK*LDB*2)
#define STG   (STG_A + STG_B)
#define SMEM_BYTES (NSTG*STG)

// MODE 1: A = g_xh gathered by token, B = g_w1h -> GELU -> g_hidden (fp16)
// MODE 2: A = g_hidden grouped rows,  B = g_w2h -> g_eout (fp16)
template<int KDIM, int NDIM, int MODE>
__global__ void __launch_bounds__(256, 2)
k_gemm_cp(int rtBase, int rtSpan)
{
    extern __shared__ char smem[];
    uint32_t sb = smem_u32(smem);

    int totalRT = g_tp[NEXP];
    int t = blockIdx.x;
    int rt = rtBase + t % rtSpan;
    int ct = t / rtSpan;
    if (rt >= totalRT) return;
    int e = 0;
    while (g_tp[e+1] <= rt) e++;
    int row0   = g_off[e] + (rt - g_tp[e]) * 128;
    int rowEnd = g_off[e+1];
    int n0 = ct * 128;

    const __half* Wh = ((MODE == 1) ? g_w1h : g_w2h) + (size_t)e * KDIM * NDIM;

    int tid = threadIdx.x, lane = tid & 31, wid = tid >> 5;
    int wm = wid >> 2, wn = wid & 3;   // 2x4 warps, each 64x32

    // ---- A loader: 2 threads/row, 32B each ----
    int lrowA = tid >> 1;
    int asub  = (tid & 1) * 16;
    int gr = row0 + lrowA;
    bool av = (gr < rowEnd);
    const __half* asrc;
    if (MODE == 1) asrc = g_xh     + (size_t)(av ? g_row_token[gr] : 0) * KDIM + asub;
    else           asrc = g_hidden + (size_t)(av ? gr : 0) * KDIM + asub;
    int asz = av ? 16 : 0;

    // ---- B loader: 8 threads/row, 32B each ----
    int lrowB = tid >> 3;
    int bsub  = (tid & 7) * 16;
    const __half* bsrc = Wh + (size_t)lrowB * NDIM + n0 + bsub;

    uint32_t aDst[2], bDst[2];
#pragma unroll
    for (int i = 0; i < 2; i++) {
        aDst[i] = sb + (uint32_t)((lrowA * LDA + asub + i * 8) * 2);
        bDst[i] = sb + STG_A + (uint32_t)((lrowB * LDB + bsub + i * 8) * 2);
    }

    float acc[4][4][4];
#pragma unroll
    for (int mi = 0; mi < 4; mi++)
#pragma unroll
        for (int ni = 0; ni < 4; ni++)
#pragma unroll
            for (int k = 0; k < 4; k++) acc[mi][ni][k] = 0.f;

    const int NKB = KDIM / BK;   // even (32 or 128)

#define ISSUE_A(c) do { \
        uint32_t so = ((c) % NSTG) * STG; \
        const __half* as_ = asrc + (c) * BK; \
        CPA16(aDst[0] + so, as_,     asz); \
        CPA16(aDst[1] + so, as_ + 8, asz); \
    } while(0)
#define ISSUE_B(c) do { \
        uint32_t so = ((c) % NSTG) * STG; \
        const __half* bs_ = bsrc + (size_t)(c) * BK * NDIM; \
        CPA16(bDst[0] + so, bs_,     16); \
        CPA16(bDst[1] + so, bs_ + 8, 16); \
    } while(0)

    // preload stages 0..3 (one commit group each); prefetch distance = 4
#pragma unroll
    for (int c = 0; c < 4; c++) { ISSUE_A(c); ISSUE_B(c); CPA_COMMIT(); }

    for (int kb = 0; kb < NKB; kb += 2) {
        CPA_WAIT2();          // stages kb, kb+1 resident (pending = kb+2, kb+3)
        __syncthreads();      // all warps past reads of stages (kb-2), (kb-1)

        bool pf = (kb + 4 < NKB);
#pragma unroll
        for (int kk = 0; kk < 4; kk++) {
            uint32_t abase = sb + ((kb + (kk >> 1)) % NSTG) * STG;
            uint32_t bbase = abase + STG_A;
            int k0 = (kk & 1) * 16;
            uint32_t afr[4][4];
#pragma unroll
            for (int mi = 0; mi < 4; mi++) {
                uint32_t addr = abase + (uint32_t)(((wm * 64 + mi * 16 + (lane & 15)) * LDA
                                                    + k0 + (lane >> 4) * 8) * 2);
                ldsm_x4(afr[mi][0], afr[mi][1], afr[mi][2], afr[mi][3], addr);
            }
            uint32_t bfr[4][2];
#pragma unroll
            for (int nb = 0; nb < 2; nb++) {
                uint32_t addr = bbase + (uint32_t)(((k0 + (lane & 15)) * LDB
                                                    + wn * 32 + nb * 16 + (lane >> 4) * 8) * 2);
                uint32_t r0, r1, r2, r3;
                ldsm_x4t(r0, r1, r2, r3, addr);
                bfr[nb*2][0] = r0;   bfr[nb*2][1] = r1;
                bfr[nb*2+1][0] = r2; bfr[nb*2+1][1] = r3;
            }
            if (pf) {
                if (kk == 0) ISSUE_A(kb + 4);
                if (kk == 1) ISSUE_B(kb + 4);
                if (kk == 2) ISSUE_A(kb + 5);
                if (kk == 3) ISSUE_B(kb + 5);
            }
            if (kk == 1) CPA_COMMIT();
#pragma unroll
            for (int mi = 0; mi < 4; mi++)
#pragma unroll
                for (int ni = 0; ni < 4; ni++)
                    mma16816(acc[mi][ni], afr[mi], bfr[ni]);
        }
        CPA_COMMIT();
    }
#undef ISSUE_A
#undef ISSUE_B

    // ---- epilogue ----
    int mrow = row0 + wm * 64 + (lane >> 2);
    int ncol = n0 + wn * 32 + (lane & 3) * 2;
#pragma unroll
    for (int mi = 0; mi < 4; mi++) {
#pragma unroll
        for (int ni = 0; ni < 4; ni++) {
            int r0r = mrow + mi * 16;
            int c   = ncol + ni * 8;
            if (MODE == 1) {
                if (r0r < rowEnd) {
                    __half2 h = __floats2half2_rn(gelu_exact(acc[mi][ni][0]),
                                                  gelu_exact(acc[mi][ni][1]));
                    *(__half2*)&g_hidden[(size_t)r0r * NDIM + c] = h;
                }
                if (r0r + 8 < rowEnd) {
                    __half2 h = __floats2half2_rn(gelu_exact(acc[mi][ni][2]),
                                                  gelu_exact(acc[mi][ni][3]));
                    *(__half2*)&g_hidden[(size_t)(r0r + 8) * NDIM + c] = h;
                }
            } else {
                if (r0r < rowEnd) {
                    __half2 h = __floats2half2_rn(acc[mi][ni][0], acc[mi][ni][1]);
                    *(__half2*)&g_eout[(size_t)r0r * NDIM + c] = h;
                }
                if (r0r + 8 < rowEnd) {
                    __half2 h = __floats2half2_rn(acc[mi][ni][2], acc[mi][ni][3]);
                    *(__half2*)&g_eout[(size_t)(r0r + 8) * NDIM + c] = h;
                }
            }
        }
    }
}

// ---------------- launch ----------------
extern "C" void kernel_launch(void* const* d_in, const int* in_sizes, int n_in,
                              void* d_out, int out_size) {
    const float* x  = (const float*)d_in[0];
    const float* rw = (const float*)d_in[1];
    const float* rb = (const float*)d_in[2];
    const float* w1 = (const float*)d_in[3];
    const float* w2 = (const float*)d_in[4];
    float* out = (float*)d_out;

    static cudaStream_t s1 = nullptr;
    static cudaEvent_t evF = nullptr, evRouter = nullptr, evRT = nullptr,
                       evW2 = nullptr, evG2B = nullptr;
    static bool init_done = false;
    if (!init_done) {
        cudaFuncSetAttribute((const void*)k_gemm_cp<HDIM, FDIM, 1>,
                             cudaFuncAttributeMaxDynamicSharedMemorySize, SMEM_BYTES);
        cudaFuncSetAttribute((const void*)k_gemm_cp<FDIM, HDIM, 2>,
                             cudaFuncAttributeMaxDynamicSharedMemorySize, SMEM_BYTES);
        cudaStreamCreateWithFlags(&s1, cudaStreamNonBlocking);
        cudaEventCreateWithFlags(&evF,      cudaEventDisableTiming);
        cudaEventCreateWithFlags(&evRouter, cudaEventDisableTiming);
        cudaEventCreateWithFlags(&evRT,     cudaEventDisableTiming);
        cudaEventCreateWithFlags(&evW2,     cudaEventDisableTiming);
        cudaEventCreateWithFlags(&evG2B,    cudaEventDisableTiming);
        init_done = true;
    }

    __half *xh_p, *w1h_p, *w2h_p;
    cudaGetSymbolAddress((void**)&xh_p,  g_xh);
    cudaGetSymbolAddress((void**)&w1h_p, g_w1h);
    cudaGetSymbolAddress((void**)&w2h_p, g_w2h);

    // fork
    cudaEventRecord(evF, 0);
    cudaStreamWaitEvent(s1, evF, 0);

    // side stream s1: init + router (+fused x convert); convert_w2 starts immediately after
    k_init0<<<1, 32, 0, s1>>>();
    k_router<<<NTOK/8, 256, 0, s1>>>((const float4*)x, (const float4*)rw, rb, (uint2*)xh_p);
    cudaEventRecord(evRouter, s1);
    k_convert_w2<<<2048, 256, 0, s1>>>((const float4*)w2, (uint2*)w2h_p);
    cudaEventRecord(evW2, s1);

    // main stream: w1 conversion, then scatter (after router), then GEMM halves
    k_convert_w1<<<4096, 256>>>((const float4*)w1, (uint2*)w1h_p);
    cudaStreamWaitEvent(0, evRouter, 0);
    k_scatter<<<(NTOK*2 + 255)/256, 256>>>();
    cudaEventRecord(evRT, 0);   // covers scatter AND convert_w1 (stream order)

    k_gemm_cp<HDIM, FDIM, 1><<<HALF_RT*(FDIM/128), 256, SMEM_BYTES>>>(0, HALF_RT);
    cudaStreamWaitEvent(s1, evRT, 0);
    k_gemm_cp<HDIM, FDIM, 1><<<HALF_RT*(FDIM/128), 256, SMEM_BYTES, s1>>>(HALF_RT, HALF_RT);

    cudaStreamWaitEvent(0, evW2, 0);
    k_gemm_cp<FDIM, HDIM, 2><<<HALF_RT*(HDIM/128), 256, SMEM_BYTES>>>(0, HALF_RT);
    k_gemm_cp<FDIM, HDIM, 2><<<HALF_RT*(HDIM/128), 256, SMEM_BYTES, s1>>>(HALF_RT, HALF_RT);
    cudaEventRecord(evG2B, s1);

    cudaStreamWaitEvent(0, evG2B, 0);
    k_combine<<<(NTOK*HDIM/8 + 255)/256, 256>>>(out);
}